// round 16
// baseline (speedup 1.0000x reference)
#include <cuda_runtime.h>
#include <cuda_bf16.h>
#include <cstdint>

#define N_NODES 50000
#define N_PAD   50176            // 784 * 64
#define N_EDGES 800000
#define DIM     256
#define KD      512              // concat(mean, root) K dimension
#define SCAN_B  1024
#define SCAN_NB 49

// ---------------- static device scratch ----------------
__device__ __nv_bfloat16 g_ahi[(size_t)N_PAD * KD];   // zero-init; pad rows never written
__device__ __nv_bfloat16 g_alo[(size_t)N_PAD * KD];
__device__ float g_h[(size_t)N_NODES * DIM];
__device__ int   g_deg[N_NODES];
__device__ float g_inv[N_NODES];
__device__ int   g_rs[N_NODES];
__device__ int   g_cur[N_NODES];
__device__ int   g_srt[N_EDGES];
__device__ int   g_bsum[64];
__device__ int   g_is64;
__device__ __nv_bfloat16 g_w1hi[DIM * KD], g_w1lo[DIM * KD];   // [n=256][k=512]
__device__ __nv_bfloat16 g_w2hi[DIM * KD], g_w2lo[DIM * KD];

// ---------------- PTX helpers (baseline ISA only — no sm_103a features) ----------------
__device__ __forceinline__ uint32_t smem_u32(const void* p) {
    uint32_t a;
    asm("{ .reg .u64 t; cvta.to.shared.u64 t, %1; cvt.u32.u64 %0, t; }" : "=r"(a) : "l"(p));
    return a;
}
__device__ __forceinline__ void cpa16(uint32_t dst, const void* src) {
    asm volatile("cp.async.cg.shared.global [%0], [%1], 16;" :: "r"(dst), "l"(src) : "memory");
}
__device__ __forceinline__ void cp_commit() {
    asm volatile("cp.async.commit_group;" ::: "memory");
}
template<int N> __device__ __forceinline__ void cp_wait() {
    asm volatile("cp.async.wait_group %0;" :: "n"(N) : "memory");
}
__device__ __forceinline__ void ldm_x4(uint32_t* r, uint32_t addr) {
    asm volatile("ldmatrix.sync.aligned.m8n8.x4.shared.b16 {%0,%1,%2,%3}, [%4];"
                 : "=r"(r[0]), "=r"(r[1]), "=r"(r[2]), "=r"(r[3]) : "r"(addr));
}
__device__ __forceinline__ void mma16816(float* c, const uint32_t* a, uint32_t b0, uint32_t b1) {
    asm volatile("mma.sync.aligned.m16n8k16.row.col.f32.bf16.bf16.f32 "
                 "{%0,%1,%2,%3}, {%4,%5,%6,%7}, {%8,%9}, {%0,%1,%2,%3};"
                 : "+f"(c[0]), "+f"(c[1]), "+f"(c[2]), "+f"(c[3])
                 : "r"(a[0]), "r"(a[1]), "r"(a[2]), "r"(a[3]), "r"(b0), "r"(b1));
}

// ---------------- CSR build (detect folded into zero kernel) ----------------
__global__ void k_zero_detect(const int* __restrict__ e32) {
    int i = blockIdx.x * blockDim.x + threadIdx.x;
    if (i < N_NODES) g_deg[i] = 0;
    if (i == 0) {
        int is64 = 1;
        for (int t = 0; t < 32; t++)
            if (e32[2 * t + 1] != 0) is64 = 0;
        g_is64 = is64;
    }
}
__device__ __forceinline__ int edge_at(const void* edge, long long idx) {
    if (g_is64) return (int)((const long long*)edge)[idx];
    return ((const int*)edge)[idx];
}
__global__ void k_hist(const void* __restrict__ edge) {
    int e = blockIdx.x * blockDim.x + threadIdx.x;
    if (e < N_EDGES) {
        int d = edge_at(edge, (long long)N_EDGES + e);
        if ((unsigned)d < (unsigned)N_NODES) atomicAdd(&g_deg[d], 1);
    }
}
__global__ void k_scan1() {
    __shared__ int s[SCAN_B];
    int i = blockIdx.x * SCAN_B + threadIdx.x;
    int v = (i < N_NODES) ? g_deg[i] : 0;
    s[threadIdx.x] = v;
    __syncthreads();
    for (int off = 1; off < SCAN_B; off <<= 1) {
        int t = (threadIdx.x >= off) ? s[threadIdx.x - off] : 0;
        __syncthreads();
        s[threadIdx.x] += t;
        __syncthreads();
    }
    if (i < N_NODES) g_rs[i] = s[threadIdx.x] - v;
    if (threadIdx.x == SCAN_B - 1) g_bsum[blockIdx.x] = s[SCAN_B - 1];
}
// scan3 with the inter-block offset computed in-kernel (replaces k_scan2)
__global__ void k_scan3() {
    __shared__ int boff;
    if (threadIdx.x == 0) {
        int a = 0;
        for (int b = 0; b < blockIdx.x; b++) a += g_bsum[b];
        boff = a;
    }
    __syncthreads();
    int i = blockIdx.x * SCAN_B + threadIdx.x;
    if (i < N_NODES) {
        int rs = g_rs[i] + boff;
        g_rs[i]  = rs;
        g_cur[i] = rs;
        int d = g_deg[i];
        g_inv[i] = 1.0f / (float)(d > 1 ? d : 1);
    }
}
__global__ void k_scatter(const void* __restrict__ edge) {
    int e = blockIdx.x * blockDim.x + threadIdx.x;
    if (e < N_EDGES) {
        int d = edge_at(edge, (long long)N_EDGES + e);
        if ((unsigned)d < (unsigned)N_NODES) {
            int s = edge_at(edge, e);
            if ((unsigned)s >= (unsigned)N_NODES) s = 0;
            int p = atomicAdd(&g_cur[d], 1);
            g_srt[p] = s;
        }
    }
}

// ---------------- weight split, BOTH layers in one launch ----------------
__global__ void k_wsplit2(const float* __restrict__ W1l, const float* __restrict__ W1r,
                          const float* __restrict__ W2l, const float* __restrict__ W2r,
                          __nv_bfloat16* __restrict__ w1h, __nv_bfloat16* __restrict__ w1l,
                          __nv_bfloat16* __restrict__ w2h, __nv_bfloat16* __restrict__ w2l) {
    int gidx = blockIdx.x * blockDim.x + threadIdx.x;
    if (gidx >= 2 * DIM * KD) return;
    int layer = gidx >= DIM * KD;
    int idx = gidx - layer * DIM * KD;
    int n = idx >> 9, k = idx & 511;
    const float* Wl = layer ? W2l : W1l;
    const float* Wr = layer ? W2r : W1r;
    float v = (k < DIM) ? Wl[n * DIM + k] : Wr[n * DIM + (k - DIM)];
    __nv_bfloat16 h = __float2bfloat16(v);
    (layer ? w2h : w1h)[idx] = h;
    (layer ? w2l : w1l)[idx] = __float2bfloat16(v - __bfloat162float(h));
}

// ---------------- split-store helper: 4 floats -> bf16 hi/lo ----------------
__device__ __forceinline__ void st_split4(__nv_bfloat16* hp, __nv_bfloat16* lp, float4 v) {
    __nv_bfloat16 h0 = __float2bfloat16(v.x), h1 = __float2bfloat16(v.y);
    __nv_bfloat16 h2 = __float2bfloat16(v.z), h3 = __float2bfloat16(v.w);
    __nv_bfloat162 a, b;
    a.x = h0; a.y = h1; b.x = h2; b.y = h3;
    ((__nv_bfloat162*)hp)[0] = a; ((__nv_bfloat162*)hp)[1] = b;
    a.x = __float2bfloat16(v.x - __bfloat162float(h0));
    a.y = __float2bfloat16(v.y - __bfloat162float(h1));
    b.x = __float2bfloat16(v.z - __bfloat162float(h2));
    b.y = __float2bfloat16(v.w - __bfloat162float(h3));
    ((__nv_bfloat162*)lp)[0] = a; ((__nv_bfloat162*)lp)[1] = b;
}
__device__ __forceinline__ void acc4(float4& a, float4 u) {
    a.x += u.x; a.y += u.y; a.z += u.z; a.w += u.w;
}

// ---------------- fused mean-agg + root-copy, output bf16 hi/lo [N_PAD x 512] ----------------
__global__ void k_aggsplit(const float* __restrict__ feat) {
    int gw   = (blockIdx.x * blockDim.x + threadIdx.x) >> 5;
    int lane = threadIdx.x & 31;
    if (gw >= N_NODES) return;
    int s0 = g_rs[gw];
    int d  = g_deg[gw];
    float4 a = make_float4(0.f, 0.f, 0.f, 0.f);
    float4 b = make_float4(0.f, 0.f, 0.f, 0.f);
    int k = 0;
    int dm4 = d & ~3;
    for (; k < dm4; k += 4) {
        int i0 = g_srt[s0 + k + 0];
        int i1 = g_srt[s0 + k + 1];
        int i2 = g_srt[s0 + k + 2];
        int i3 = g_srt[s0 + k + 3];
        const float4* r0 = reinterpret_cast<const float4*>(feat + (size_t)i0 * DIM);
        const float4* r1 = reinterpret_cast<const float4*>(feat + (size_t)i1 * DIM);
        const float4* r2 = reinterpret_cast<const float4*>(feat + (size_t)i2 * DIM);
        const float4* r3 = reinterpret_cast<const float4*>(feat + (size_t)i3 * DIM);
        float4 u0 = __ldg(&r0[lane]),      u1 = __ldg(&r1[lane]);
        float4 u2 = __ldg(&r2[lane]),      u3 = __ldg(&r3[lane]);
        float4 v0 = __ldg(&r0[lane + 32]), v1 = __ldg(&r1[lane + 32]);
        float4 v2 = __ldg(&r2[lane + 32]), v3 = __ldg(&r3[lane + 32]);
        acc4(a, u0); acc4(a, u1); acc4(a, u2); acc4(a, u3);
        acc4(b, v0); acc4(b, v1); acc4(b, v2); acc4(b, v3);
    }
    for (; k < d; k++) {
        int src = g_srt[s0 + k];
        const float4* r = reinterpret_cast<const float4*>(feat + (size_t)src * DIM);
        acc4(a, __ldg(&r[lane]));
        acc4(b, __ldg(&r[lane + 32]));
    }
    float sc = g_inv[gw];
    a.x *= sc; a.y *= sc; a.z *= sc; a.w *= sc;
    b.x *= sc; b.y *= sc; b.z *= sc; b.w *= sc;
    const float4* rr = reinterpret_cast<const float4*>(feat + (size_t)gw * DIM);
    float4 c0 = __ldg(&rr[lane]);
    float4 c1 = __ldg(&rr[lane + 32]);
    __nv_bfloat16* hb = g_ahi + (size_t)gw * KD;
    __nv_bfloat16* lb = g_alo + (size_t)gw * KD;
    st_split4(hb + 4 * lane,       lb + 4 * lane,       a);
    st_split4(hb + 128 + 4 * lane, lb + 128 + 4 * lane, b);
    st_split4(hb + 256 + 4 * lane, lb + 256 + 4 * lane, c0);
    st_split4(hb + 384 + 4 * lane, lb + 384 + 4 * lane, c1);
}

// ---------------- HMMA GEMM: C[64m x 256n] per CTA, 128 threads, BK=16, 3-stage pipe ----------------
// 2 CTAs/SM: independent sync domains per SMSP keep the tensor pipe fed.
#define RS16      48                       // padded row stride in bytes (16+8 halves)
#define AHI_OFF   0                        // 64 x 48  = 3072
#define ALO_OFF   3072
#define WHI_OFF   6144                     // 256 x 48 = 12288
#define WLO_OFF   18432
#define STAGE_SZ  30720
#define BIAS_OFF  92160                    // 3 stages end at 92160
#define SS_OFF    93184                    // 64 floats
#define SM_TOTAL  93440
#define NSTAGE    32                       // 512 / 16

__device__ __forceinline__ void load_stage16(uint32_t sb, int buf, int m0, int k0,
                                             const __nv_bfloat16* whi, const __nv_bfloat16* wlo,
                                             int tid) {
    uint32_t base = sb + buf * STAGE_SZ;
    {   // A hi/lo: 64 rows x 2 chunks = 128 chunks each -> 1 per thread
        int row = tid >> 1, seg = tid & 1;
        size_t gofs = (size_t)(m0 + row) * KD + k0 + seg * 8;
        cpa16(base + AHI_OFF + row * RS16 + seg * 16, g_ahi + gofs);
        cpa16(base + ALO_OFF + row * RS16 + seg * 16, g_alo + gofs);
    }
#pragma unroll
    for (int u = 0; u < 4; u++) {          // W hi/lo: 256 rows x 2 chunks = 512 each -> 4 per thread
        int c = u * 128 + tid;
        int row = c >> 1, seg = c & 1;
        size_t gofs = (size_t)row * KD + k0 + seg * 8;
        cpa16(base + WHI_OFF + row * RS16 + seg * 16, whi + gofs);
        cpa16(base + WLO_OFF + row * RS16 + seg * 16, wlo + gofs);
    }
    cp_commit();
}

__global__ __launch_bounds__(128, 2) void k_gemm_mma(
    const __nv_bfloat16* __restrict__ whi, const __nv_bfloat16* __restrict__ wlo,
    const float* __restrict__ bias, float* __restrict__ out, int relu) {
    extern __shared__ char smem[];
    uint32_t sb = smem_u32(smem);
    int tid = threadIdx.x, wid = tid >> 5, lane = tid & 31;
    int wc = wid;                           // warp grid 1 x 4, warp tile 64 x 64
    int m0 = blockIdx.x * 64;

    float* bsm = (float*)(smem + BIAS_OFF);
    float* ssm = (float*)(smem + SS_OFF);
    bsm[tid]       = bias[tid];
    bsm[tid + 128] = bias[tid + 128];
    if (tid < 64) ssm[tid] = 0.f;

    float acc[4][8][4];
#pragma unroll
    for (int i = 0; i < 4; i++)
#pragma unroll
        for (int j = 0; j < 8; j++)
#pragma unroll
            for (int q = 0; q < 4; q++) acc[i][j][q] = 0.f;

    load_stage16(sb, 0, m0, 0,  whi, wlo, tid);
    load_stage16(sb, 1, m0, 16, whi, wlo, tid);

    int moff = lane & 15;                   // ldmatrix row-within-tile
    uint32_t ksegb = (uint32_t)((lane >> 4) * 16);   // byte offset of k-half

    for (int s = 0; s < NSTAGE; s++) {
        cp_wait<1>();                       // stage s data resident (only s+1 may pend)
        __syncthreads();                    // all threads past compute(s-1): buf (s+2)%3 free
        if (s + 2 < NSTAGE) load_stage16(sb, (s + 2) % 3, m0, (s + 2) * 16, whi, wlo, tid);
        else                cp_commit();    // keep group accounting aligned

        uint32_t stg = sb + (uint32_t)((s % 3) * STAGE_SZ);
        uint32_t ah[4][4], al[4][4], bh[4][4], bl[4][4];
#pragma unroll
        for (int i = 0; i < 4; i++) {
            uint32_t ao = (uint32_t)((i * 16 + moff) * RS16) + ksegb;
            ldm_x4(ah[i], stg + AHI_OFF + ao);
            ldm_x4(al[i], stg + ALO_OFF + ao);
        }
#pragma unroll
        for (int p = 0; p < 4; p++) {
            uint32_t bo = (uint32_t)((wc * 64 + p * 16 + moff) * RS16) + ksegb;
            ldm_x4(bh[p], stg + WHI_OFF + bo);
            ldm_x4(bl[p], stg + WLO_OFF + bo);
        }
#pragma unroll
        for (int i = 0; i < 4; i++)
#pragma unroll
            for (int j = 0; j < 8; j++) {
                int p = j >> 1, q = j & 1;
                mma16816(acc[i][j], ah[i], bh[p][q], bh[p][q + 2]);   // hi*hi
                mma16816(acc[i][j], ah[i], bl[p][q], bl[p][q + 2]);   // hi*lo
                mma16816(acc[i][j], al[i], bh[p][q], bh[p][q + 2]);   // lo*hi
            }
    }

    // ---------------- epilogue: bias + row L2 norm + (relu) + store ----------------
    int qr = lane >> 2, qc = lane & 3;
#pragma unroll
    for (int i = 0; i < 4; i++) {
        int r0 = i * 16 + qr;               // rows r0 and r0+8
        float s0 = 0.f, s1 = 0.f;
#pragma unroll
        for (int j = 0; j < 8; j++) {
            int col = wc * 64 + j * 8 + qc * 2;
            float b0 = bsm[col], b1 = bsm[col + 1];
            acc[i][j][0] += b0; acc[i][j][1] += b1;
            acc[i][j][2] += b0; acc[i][j][3] += b1;
            s0 = fmaf(acc[i][j][0], acc[i][j][0], s0);
            s0 = fmaf(acc[i][j][1], acc[i][j][1], s0);
            s1 = fmaf(acc[i][j][2], acc[i][j][2], s1);
            s1 = fmaf(acc[i][j][3], acc[i][j][3], s1);
        }
        s0 += __shfl_xor_sync(0xffffffffu, s0, 1);
        s0 += __shfl_xor_sync(0xffffffffu, s0, 2);
        s1 += __shfl_xor_sync(0xffffffffu, s1, 1);
        s1 += __shfl_xor_sync(0xffffffffu, s1, 2);
        if (qc == 0) {
            atomicAdd(&ssm[r0], s0);
            atomicAdd(&ssm[r0 + 8], s1);
        }
    }
    __syncthreads();

#pragma unroll
    for (int i = 0; i < 4; i++) {
        int r0 = i * 16 + qr;
        float sc0 = 1.0f / fmaxf(sqrtf(ssm[r0]),     1e-12f);
        float sc1 = 1.0f / fmaxf(sqrtf(ssm[r0 + 8]), 1e-12f);
        int g0 = m0 + r0, g1 = g0 + 8;
#pragma unroll
        for (int j = 0; j < 8; j++) {
            int col = wc * 64 + j * 8 + qc * 2;
            float2 v0, v1;
            v0.x = acc[i][j][0] * sc0; v0.y = acc[i][j][1] * sc0;
            v1.x = acc[i][j][2] * sc1; v1.y = acc[i][j][3] * sc1;
            if (relu) {
                v0.x = fmaxf(v0.x, 0.f); v0.y = fmaxf(v0.y, 0.f);
                v1.x = fmaxf(v1.x, 0.f); v1.y = fmaxf(v1.y, 0.f);
            }
            if (g0 < N_NODES) *reinterpret_cast<float2*>(out + (size_t)g0 * DIM + col) = v0;
            if (g1 < N_NODES) *reinterpret_cast<float2*>(out + (size_t)g1 * DIM + col) = v1;
        }
    }
}

// ---------------- launch ----------------
extern "C" void kernel_launch(void* const* d_in, const int* in_sizes, int n_in,
                              void* d_out, int out_size) {
    const float* x    = (const float*)d_in[0];
    const void*  edge = d_in[1];
    const float* W1l  = (const float*)d_in[2];
    const float* b1l  = (const float*)d_in[3];
    const float* W1r  = (const float*)d_in[4];
    const float* W2l  = (const float*)d_in[5];
    const float* b2l  = (const float*)d_in[6];
    const float* W2r  = (const float*)d_in[7];
    float*       out  = (float*)d_out;

    float* p_h;
    __nv_bfloat16 *p_w1h, *p_w1l, *p_w2h, *p_w2l;
    cudaGetSymbolAddress((void**)&p_h,   g_h);
    cudaGetSymbolAddress((void**)&p_w1h, g_w1hi);
    cudaGetSymbolAddress((void**)&p_w1l, g_w1lo);
    cudaGetSymbolAddress((void**)&p_w2h, g_w2hi);
    cudaGetSymbolAddress((void**)&p_w2l, g_w2lo);

    cudaFuncSetAttribute(k_gemm_mma, cudaFuncAttributeMaxDynamicSharedMemorySize, SM_TOTAL);

    // CSR build
    k_zero_detect<<<(N_NODES + 255) / 256, 256>>>((const int*)edge);
    k_hist<<<(N_EDGES + 255) / 256, 256>>>(edge);
    k_scan1<<<SCAN_NB, SCAN_B>>>();
    k_scan3<<<SCAN_NB, SCAN_B>>>();
    k_scatter<<<(N_EDGES + 255) / 256, 256>>>(edge);

    // weight split (both layers, one launch)
    k_wsplit2<<<(2 * DIM * KD + 255) / 256, 256>>>(W1l, W1r, W2l, W2r,
                                                   p_w1h, p_w1l, p_w2h, p_w2l);

    // layer 1
    k_aggsplit<<<(N_NODES * 32 + 255) / 256, 256>>>(x);
    k_gemm_mma<<<N_PAD / 64, 128, SM_TOTAL>>>(p_w1h, p_w1l, b1l, p_h, 1);

    // layer 2
    k_aggsplit<<<(N_NODES * 32 + 255) / 256, 256>>>(p_h);
    k_gemm_mma<<<N_PAD / 64, 128, SM_TOTAL>>>(p_w2h, p_w2l, b2l, out, 0);
}